// round 6
// baseline (speedup 1.0000x reference)
#include <cuda_runtime.h>
#include <cuda_bf16.h>

#define K_F 16
#define T_TYPES 4
#define OUT_W (K_F * T_TYPES)
#define PI_F 3.14159265358979323846f
#define BLK 256
#define EDGES_PER_BLK (BLK * 2)
#define TYPE_CAP (1 << 20)

// node -> matched one-hot type (-1 if none); filled by prep_kernel
__device__ signed char g_type[TYPE_CAP];

// Fused: zero the output AND build the per-node type table.
__global__ void prep_kernel(float4* __restrict__ out4, int n4,
                            const float* __restrict__ feat,
                            const float* __restrict__ ftu,
                            int V, int use_table)
{
    int i = blockIdx.x * blockDim.x + threadIdx.x;
    if (i < n4) out4[i] = make_float4(0.f, 0.f, 0.f, 0.f);
    if (use_table && i < V) {
        float fv = feat[i];
        signed char t = -1;
        #pragma unroll
        for (int j = 0; j < T_TYPES; j++)
            if (fv == ftu[j]) t = (signed char)j;
        g_type[i] = t;
    }
}

__global__ void __launch_bounds__(BLK) edge_kernel(
    const float* __restrict__ feat,      // (V,1)  (fallback only)
    const float* __restrict__ dist,      // (E,1)
    const int*   __restrict__ src,       // (E,)
    const int*   __restrict__ dst,       // (E,)
    const float* __restrict__ cutoffs,   // (K,)
    const float* __restrict__ means,     // (K,)
    const float* __restrict__ scaling,   // (K,)
    const float* __restrict__ ftu,       // (T,)
    float*       __restrict__ out,       // (V, T*K)
    int E, int use_table)
{
    __shared__ float s_mean[K_F], s_nscal[K_F], s_cut[K_F], s_ftu[T_TYPES];
    __shared__ int s_unicos;
    // stride 5 float4 per edge: conflict-free for write (le=t / t+256) and
    // transposed read (el = q*4 + i) phases (R3-verified pattern).
    __shared__ float4 s_val[EDGES_PER_BLK * 5];
    __shared__ int s_code[EDGES_PER_BLK];   // dst*4+type, or -1

    int tid = threadIdx.x;
    if (tid < K_F) {
        s_mean[tid]  = means[tid];
        s_nscal[tid] = -scaling[tid];
        s_cut[tid]   = cutoffs[tid];
    }
    if (tid < T_TYPES) s_ftu[tid] = ftu[tid];
    if (tid == 0) {
        int u = 1;
        #pragma unroll
        for (int k = 1; k < K_F; k++) u &= (cutoffs[k] == cutoffs[0]);
        s_unicos = u;
    }
    __syncthreads();

    int base = blockIdx.x * EDGES_PER_BLK;

    // Batch all global loads up front (max MLP on the 2-level gather chains).
    int e0 = base + tid;
    int e1 = base + BLK + tid;
    bool v0ok = (e0 < E), v1ok = (e1 < E);
    float d0 = 0.f, d1 = 0.f;
    int   s0 = 0, s1 = 0, dd0 = 0, dd1 = 0;
    if (v0ok) { d0 = dist[e0]; s0 = src[e0]; dd0 = dst[e0]; }
    if (v1ok) { d1 = dist[e1]; s1 = src[e1]; dd1 = dst[e1]; }

    int ty0 = -1, ty1 = -1;
    if (use_table) {
        if (v0ok) ty0 = g_type[s0];
        if (v1ok) ty1 = g_type[s1];
    } else {
        float fv0 = v0ok ? __ldg(&feat[s0]) : -1.f;
        float fv1 = v1ok ? __ldg(&feat[s1]) : -1.f;
        #pragma unroll
        for (int j = 0; j < T_TYPES; j++) {
            if (v0ok && fv0 == s_ftu[j]) ty0 = j;
            if (v1ok && fv1 == s_ftu[j]) ty1 = j;
        }
    }

    int unicos = s_unicos;

    // ---- edge 0: compute + stage (v[] regs reused for edge 1) ----
    {
        float v[K_F];
        if (ty0 >= 0) {
            if (unicos) {
                float cu = s_cut[0];
                float cv = (d0 <= cu) ? 0.5f * (__cosf(PI_F * d0 / cu) + 1.0f) : 0.0f;
                #pragma unroll
                for (int k = 0; k < K_F; k++) {
                    float dm = d0 - s_mean[k];
                    v[k] = cv * __expf(s_nscal[k] * dm * dm);
                }
            } else {
                #pragma unroll
                for (int k = 0; k < K_F; k++) {
                    float cu = s_cut[k];
                    float cv = (d0 <= cu) ? 0.5f * (__cosf(PI_F * d0 / cu) + 1.0f) : 0.0f;
                    float dm = d0 - s_mean[k];
                    v[k] = cv * __expf(s_nscal[k] * dm * dm);
                }
            }
        } else {
            #pragma unroll
            for (int k = 0; k < K_F; k++) v[k] = 0.0f;
        }
        float4* slot = &s_val[tid * 5];
        slot[0] = make_float4(v[0],  v[1],  v[2],  v[3]);
        slot[1] = make_float4(v[4],  v[5],  v[6],  v[7]);
        slot[2] = make_float4(v[8],  v[9],  v[10], v[11]);
        slot[3] = make_float4(v[12], v[13], v[14], v[15]);
        s_code[tid] = (ty0 >= 0) ? (dd0 * T_TYPES + ty0) : -1;
    }

    // ---- edge 1: compute + stage ----
    {
        float v[K_F];
        if (ty1 >= 0) {
            if (unicos) {
                float cu = s_cut[0];
                float cv = (d1 <= cu) ? 0.5f * (__cosf(PI_F * d1 / cu) + 1.0f) : 0.0f;
                #pragma unroll
                for (int k = 0; k < K_F; k++) {
                    float dm = d1 - s_mean[k];
                    v[k] = cv * __expf(s_nscal[k] * dm * dm);
                }
            } else {
                #pragma unroll
                for (int k = 0; k < K_F; k++) {
                    float cu = s_cut[k];
                    float cv = (d1 <= cu) ? 0.5f * (__cosf(PI_F * d1 / cu) + 1.0f) : 0.0f;
                    float dm = d1 - s_mean[k];
                    v[k] = cv * __expf(s_nscal[k] * dm * dm);
                }
            }
        } else {
            #pragma unroll
            for (int k = 0; k < K_F; k++) v[k] = 0.0f;
        }
        float4* slot = &s_val[(BLK + tid) * 5];
        slot[0] = make_float4(v[0],  v[1],  v[2],  v[3]);
        slot[1] = make_float4(v[4],  v[5],  v[6],  v[7]);
        slot[2] = make_float4(v[8],  v[9],  v[10], v[11]);
        slot[3] = make_float4(v[12], v[13], v[14], v[15]);
        s_code[BLK + tid] = (ty1 >= 0) ? (dd1 * T_TYPES + ty1) : -1;
    }

    __syncthreads();

    // Transposed RED: quad q, chunk c = tid&3; per step the quad's 4 red.v4
    // cover one edge's contiguous 64B-aligned output region.
    int q = tid >> 2;
    int c = tid & 3;
    #pragma unroll
    for (int pass = 0; pass < 2; pass++) {
        #pragma unroll
        for (int i = 0; i < 4; i++) {
            int el = pass * BLK + q * 4 + i;
            int code = s_code[el];
            if (code >= 0) {
                float4 val = s_val[el * 5 + c];
                float* addr = out + ((size_t)code << 4) + (c << 2);
                asm volatile(
                    "red.global.add.v4.f32 [%0], {%1, %2, %3, %4};"
                    :: "l"(addr), "f"(val.x), "f"(val.y), "f"(val.z), "f"(val.w)
                    : "memory");
            }
        }
    }
}

extern "C" void kernel_launch(void* const* d_in, const int* in_sizes, int n_in,
                              void* d_out, int out_size)
{
    const float* feat    = (const float*)d_in[0];
    const float* dist    = (const float*)d_in[1];
    const int*   src     = (const int*)  d_in[2];
    const int*   dst     = (const int*)  d_in[3];
    const float* cutoffs = (const float*)d_in[4];
    const float* means   = (const float*)d_in[5];
    const float* scaling = (const float*)d_in[6];
    const float* ftu     = (const float*)d_in[7];
    float* out = (float*)d_out;

    int E = in_sizes[2];
    int V = in_sizes[0];
    int use_table = (V <= TYPE_CAP) ? 1 : 0;

    int n4 = out_size / 4;
    int prep_threads = (n4 > V) ? n4 : V;
    prep_kernel<<<(prep_threads + 255) / 256, 256>>>(
        (float4*)out, n4, feat, ftu, V, use_table);

    int blocks = (E + EDGES_PER_BLK - 1) / EDGES_PER_BLK;
    edge_kernel<<<blocks, BLK>>>(
        feat, dist, src, dst, cutoffs, means, scaling, ftu, out, E, use_table);
}